// round 4
// baseline (speedup 1.0000x reference)
#include <cuda_runtime.h>
#include <cstdint>

// ============================================================================
// Problem: x[8,8192,512] f32, w_up[2048,512] f32, w_down[512,2048] f32
// BitNet b1.58 FFN. All math after quantization is exact in int8 x int8 -> s32.
// ============================================================================
#define TOKENS 65536
#define DMODEL 512
#define DFF    2048
#define WELEMS (DFF * DMODEL)

// GEMM tiling
#define NSTAGE 4
#define CH     64            // K bytes per chunk (int8)
#define PITCH  80            // smem row pitch: 5*16 -> conflict-free ldmatrix
#define TILEB  (128 * PITCH) // 10240 per operand tile
#define STAGEB (2 * TILEB)   // 20480
#define SMEM_BYTES (NSTAGE * STAGEB)  // 81920

// ============================================================================
// Device scratch (allocation-free)
// ============================================================================
__device__ float       g_part[2][256];
__device__ float       g_wscale[2];
__device__ int8_t      g_wup_q[WELEMS];          // ternary {-1,0,1}, [2048,512]
__device__ int8_t      g_wdn_q[WELEMS];          // ternary, [512,2048]
__device__ int8_t      g_xq[TOKENS * DMODEL];    // per-token int8 x
__device__ float       g_xinv[TOKENS];           // clip(max|x|,eps)/127
__device__ int         g_rowmax[TOKENS];         // max h int per token
__device__ int8_t      g_h[TOKENS * DFF];        // h ints [0,127]; then requantized

// ============================================================================
// Small helpers
// ============================================================================
__device__ __forceinline__ uint32_t smem_u32(const void* p) {
    uint32_t a;
    asm("{ .reg .u64 t; cvta.to.shared.u64 t, %1; cvt.u32.u64 %0, t; }" : "=r"(a) : "l"(p));
    return a;
}
__device__ __forceinline__ void cp16(uint32_t dst, const void* src) {
    asm volatile("cp.async.cg.shared.global [%0], [%1], 16;"
                 :: "r"(dst), "l"(__cvta_generic_to_global(src)));
}
#define CP_COMMIT() asm volatile("cp.async.commit_group;")
#define CP_WAIT2()  asm volatile("cp.async.wait_group 2;")

__device__ __forceinline__ void ldsm4(uint32_t& r0, uint32_t& r1, uint32_t& r2, uint32_t& r3,
                                      uint32_t addr) {
    asm volatile("ldmatrix.sync.aligned.m8n8.x4.shared.b16 {%0,%1,%2,%3}, [%4];"
                 : "=r"(r0), "=r"(r1), "=r"(r2), "=r"(r3) : "r"(addr));
}
__device__ __forceinline__ void mma_s8(int* c, const uint32_t* a, uint32_t b0, uint32_t b1) {
    asm volatile("mma.sync.aligned.m16n8k32.row.col.s32.s8.s8.s32 "
                 "{%0,%1,%2,%3},{%4,%5,%6,%7},{%8,%9},{%0,%1,%2,%3};"
                 : "+r"(c[0]), "+r"(c[1]), "+r"(c[2]), "+r"(c[3])
                 : "r"(a[0]), "r"(a[1]), "r"(a[2]), "r"(a[3]), "r"(b0), "r"(b1));
}

// ============================================================================
// Prep kernels (fused: both weights in one launch, selected by blockIdx.y)
// ============================================================================
__global__ void k_abs_both(const float* __restrict__ w0, const float* __restrict__ w1) {
    __shared__ float red[256];
    int which = blockIdx.y;
    const float* w = which ? w1 : w0;
    int tid = threadIdx.x;
    float s = 0.0f;
    for (int i = blockIdx.x * 256 + tid; i < WELEMS; i += 256 * 256)
        s += fabsf(w[i]);
    red[tid] = s;
    __syncthreads();
    for (int o = 128; o > 0; o >>= 1) {
        if (tid < o) red[tid] += red[tid + o];
        __syncthreads();
    }
    if (tid == 0) g_part[which][blockIdx.x] = red[0];
}

__global__ void k_finalize() {
    __shared__ float s0[256], s1[256];
    int t = threadIdx.x;
    s0[t] = g_part[0][t];
    s1[t] = g_part[1][t];
    __syncthreads();
    for (int o = 128; o > 0; o >>= 1) {
        if (t < o) { s0[t] += s0[t + o]; s1[t] += s1[t + o]; }
        __syncthreads();
    }
    if (t == 0) {
        g_wscale[0] = fmaxf(s0[0] / (float)WELEMS, 1e-5f);
        g_wscale[1] = fmaxf(s1[0] / (float)WELEMS, 1e-5f);
    }
}

__global__ void k_wquant_both(const float* __restrict__ w0, const float* __restrict__ w1) {
    int which = blockIdx.y;
    const float* w = which ? w1 : w0;
    int i = blockIdx.x * 256 + threadIdx.x;
    float ws = g_wscale[which];
    float4 v = ((const float4*)w)[i];
    int t0 = (int)fminf(fmaxf(rintf(v.x / ws), -1.f), 1.f);
    int t1 = (int)fminf(fmaxf(rintf(v.y / ws), -1.f), 1.f);
    int t2 = (int)fminf(fmaxf(rintf(v.z / ws), -1.f), 1.f);
    int t3 = (int)fminf(fmaxf(rintf(v.w / ws), -1.f), 1.f);
    int8_t* dst = which ? g_wdn_q : g_wup_q;
    *(char4*)(dst + i * 4) = make_char4((char)t0, (char)t1, (char)t2, (char)t3);
}

__global__ void k_xquant(const float* __restrict__ x) {
    __shared__ float wmax[4];
    int token = blockIdx.x;
    int tid = threadIdx.x, wid = tid >> 5, lid = tid & 31;
    float4 v = ((const float4*)(x + (size_t)token * DMODEL))[tid];
    float a = fmaxf(fmaxf(fabsf(v.x), fabsf(v.y)), fmaxf(fabsf(v.z), fabsf(v.w)));
    #pragma unroll
    for (int o = 16; o > 0; o >>= 1) a = fmaxf(a, __shfl_xor_sync(0xffffffffu, a, o));
    if (lid == 0) wmax[wid] = a;
    __syncthreads();
    a = fmaxf(fmaxf(wmax[0], wmax[1]), fmaxf(wmax[2], wmax[3]));
    float amaxc = fmaxf(a, 1e-5f);
    float s = 127.0f / amaxc;
    int q0 = (int)fminf(fmaxf(rintf(v.x * s), -128.f), 127.f);
    int q1 = (int)fminf(fmaxf(rintf(v.y * s), -128.f), 127.f);
    int q2 = (int)fminf(fmaxf(rintf(v.z * s), -128.f), 127.f);
    int q3 = (int)fminf(fmaxf(rintf(v.w * s), -128.f), 127.f);
    *(char4*)(g_xq + token * DMODEL + tid * 4) = make_char4((char)q0, (char)q1, (char)q2, (char)q3);
    if (tid == 0) {
        g_xinv[token] = amaxc / 127.0f;
        g_rowmax[token] = 0;
    }
}

// Requantize h in place: h' = rint(h * 127/clip(rowmax,eps))
__global__ void k_hrequant() {
    int idx = blockIdx.x * 256 + threadIdx.x;     // one 16B chunk
    int token = (idx * 16) >> 11;                 // 2048 per token
    float f = 127.0f / fmaxf((float)g_rowmax[token], 1e-5f);
    uint4 raw = *(const uint4*)(g_h + (size_t)idx * 16);
    uint32_t rw[4] = {raw.x, raw.y, raw.z, raw.w};
    uint32_t out[4];
    #pragma unroll
    for (int u = 0; u < 4; ++u) {
        uint32_t b = rw[u], o = 0;
        #pragma unroll
        for (int j = 0; j < 4; ++j) {
            int q = (int)fminf(rintf((float)((b >> (8 * j)) & 0xff) * f), 127.0f);
            o |= ((uint32_t)q & 0xff) << (8 * j);
        }
        out[u] = o;
    }
    *(uint4*)(g_h + (size_t)idx * 16) = make_uint4(out[0], out[1], out[2], out[3]);
}

// ============================================================================
// int8 GEMM core: C[128,128] += A[128,K] * B[128,K]^T  (both row-major K-last)
// 256 threads, 8 warps in 4(m) x 2(n); warp tile 32x64; mma m16n8k32.
// ============================================================================
template<int NK, int K>
__device__ __forceinline__ void gemm_s8_core(const int8_t* __restrict__ Ag,
                                             const int8_t* __restrict__ Bg,
                                             int m0, int n0, char* smem,
                                             int (&acc)[2][8][4]) {
    const int tid = threadIdx.x, lane = tid & 31, wid = tid >> 5;
    const int wm = wid & 3, wn = wid >> 2;

    // ---- stage loader: 1024 x 16B cp.async (A 512, B 512) ----
    auto load_chunk = [&](int kc, int buf) {
        char* st = smem + buf * STAGEB;
        #pragma unroll
        for (int t = 0; t < 4; ++t) {
            int i = tid + t * 256;
            int isB = i >> 9, idx = i & 511;
            int row = idx >> 2, c = idx & 3;
            const int8_t* src = (isB ? Bg + (size_t)(n0 + row) * K
                                     : Ag + (size_t)(m0 + row) * K) + kc * CH + c * 16;
            cp16(smem_u32(st + isB * TILEB + row * PITCH + c * 16), src);
        }
    };

    // fragment base addresses (per-lane)
    const uint32_t a_addr0 = smem_u32(smem + (wm * 32 + (lane & 15)) * PITCH + (lane >> 4) * 16);
    const uint32_t b_addr0 = smem_u32(smem + TILEB +
                                      (wn * 64 + ((lane >> 4) * 8) + (lane & 7)) * PITCH +
                                      ((lane >> 3) & 1) * 16);

    auto compute_chunk = [&](int buf) {
        uint32_t abase = a_addr0 + buf * STAGEB;
        uint32_t bbase = b_addr0 + buf * STAGEB;
        #pragma unroll
        for (int s = 0; s < 2; ++s) {                    // two k32 steps per 64B chunk
            uint32_t a[2][4];
            #pragma unroll
            for (int im = 0; im < 2; ++im)
                ldsm4(a[im][0], a[im][1], a[im][2], a[im][3],
                      abase + im * 16 * PITCH + s * 32);
            uint32_t b[4][4];
            #pragma unroll
            for (int jn = 0; jn < 4; ++jn)
                ldsm4(b[jn][0], b[jn][1], b[jn][2], b[jn][3],
                      bbase + jn * 16 * PITCH + s * 32);
            #pragma unroll
            for (int im = 0; im < 2; ++im)
                #pragma unroll
                for (int j = 0; j < 8; ++j)
                    mma_s8(acc[im][j], a[im], b[j >> 1][(j & 1) * 2], b[j >> 1][(j & 1) * 2 + 1]);
        }
    };

    // ---- 4-stage pipeline ----
    #pragma unroll
    for (int p = 0; p < 3; ++p) { load_chunk(p, p); CP_COMMIT(); }

    #pragma unroll 1
    for (int kc = 0; kc < NK; ++kc) {
        CP_WAIT2();
        __syncthreads();
        if (kc + 3 < NK) load_chunk(kc + 3, (kc + 3) & 3);
        CP_COMMIT();
        compute_chunk(kc & 3);
    }
}

// ---- GEMM1: h = clamp(rint(relu(Xq @ WupT)) * scales) -> int8 + rowmax ----
// m_base: token-block offset (GEMM1 is launched twice, half the M range each,
// so that the fixed ncu capture position lands on a GEMM launch).
__global__ void __launch_bounds__(256) k_gemm1(int m_base) {
    extern __shared__ char smem[];
    const int tid = threadIdx.x, lane = tid & 31, wid = tid >> 5;
    const int wm = wid & 3, wn = wid >> 2;
    const int m0 = (m_base + blockIdx.y) * 128, n0 = blockIdx.x * 128;

    int acc[2][8][4];
    #pragma unroll
    for (int im = 0; im < 2; ++im)
        #pragma unroll
        for (int j = 0; j < 8; ++j)
            #pragma unroll
            for (int q = 0; q < 4; ++q) acc[im][j][q] = 0;

    gemm_s8_core<DMODEL / CH, DMODEL>(g_xq, g_wup_q, m0, n0, smem, acc);

    const float ws = g_wscale[0];
    const int rbase = wm * 32 + (lane >> 2);
    float sA[2][2];
    int lmax[2][2];
    #pragma unroll
    for (int im = 0; im < 2; ++im)
        #pragma unroll
        for (int h = 0; h < 2; ++h) {
            sA[im][h] = ws * g_xinv[m0 + rbase + im * 16 + h * 8];
            lmax[im][h] = 0;
        }

    #pragma unroll
    for (int im = 0; im < 2; ++im)
        #pragma unroll
        for (int j = 0; j < 8; ++j) {
            int col = n0 + wn * 64 + j * 8 + 2 * (lane & 3);
            #pragma unroll
            for (int h = 0; h < 2; ++h) {
                int tok = m0 + rbase + im * 16 + h * 8;
                float v0 = fmaxf((float)acc[im][j][h * 2 + 0] * sA[im][h], 0.0f);
                float v1 = fmaxf((float)acc[im][j][h * 2 + 1] * sA[im][h], 0.0f);
                int q0 = min(__float2int_rn(v0), 127);
                int q1 = min(__float2int_rn(v1), 127);
                lmax[im][h] = max(lmax[im][h], max(q0, q1));
                *(char2*)(g_h + (size_t)tok * DFF + col) = make_char2((char)q0, (char)q1);
            }
        }

    // block-level rowmax reduce, then global atomicMax
    __syncthreads();
    int* smax = (int*)smem;
    if (tid < 128) smax[tid] = 0;
    __syncthreads();
    #pragma unroll
    for (int im = 0; im < 2; ++im)
        #pragma unroll
        for (int h = 0; h < 2; ++h)
            atomicMax(&smax[rbase + im * 16 + h * 8], lmax[im][h]);
    __syncthreads();
    if (tid < 128) atomicMax(&g_rowmax[m0 + tid], smax[tid]);
}

// ---- GEMM2: out = (Hq @ WdnT) * (wscale_dn * rowmax/127) -------------------
__global__ void __launch_bounds__(256) k_gemm2(float* __restrict__ out) {
    extern __shared__ char smem[];
    const int tid = threadIdx.x, lane = tid & 31, wid = tid >> 5;
    const int wm = wid & 3, wn = wid >> 2;
    const int m0 = blockIdx.y * 128, n0 = blockIdx.x * 128;

    int acc[2][8][4];
    #pragma unroll
    for (int im = 0; im < 2; ++im)
        #pragma unroll
        for (int j = 0; j < 8; ++j)
            #pragma unroll
            for (int q = 0; q < 4; ++q) acc[im][j][q] = 0;

    gemm_s8_core<DFF / CH, DFF>(g_h, g_wdn_q, m0, n0, smem, acc);

    const float ws = g_wscale[1];
    const int rbase = wm * 32 + (lane >> 2);
    float ofac[2][2];
    #pragma unroll
    for (int im = 0; im < 2; ++im)
        #pragma unroll
        for (int h = 0; h < 2; ++h) {
            int tok = m0 + rbase + im * 16 + h * 8;
            ofac[im][h] = ws * fmaxf((float)g_rowmax[tok], 1e-5f) * (1.0f / 127.0f);
        }

    #pragma unroll
    for (int im = 0; im < 2; ++im)
        #pragma unroll
        for (int j = 0; j < 8; ++j) {
            int col = n0 + wn * 64 + j * 8 + 2 * (lane & 3);
            #pragma unroll
            for (int h = 0; h < 2; ++h) {
                int tok = m0 + rbase + im * 16 + h * 8;
                float2 o = make_float2((float)acc[im][j][h * 2 + 0] * ofac[im][h],
                                       (float)acc[im][j][h * 2 + 1] * ofac[im][h]);
                *(float2*)(out + (size_t)tok * DMODEL + col) = o;
            }
        }
}

// ============================================================================
// Launch — order matters: the harness's ncu capture lands on the 5th/6th
// launch, which below is k_gemm1 (both positions), so next round's profile
// shows the GEMM.
// ============================================================================
extern "C" void kernel_launch(void* const* d_in, const int* in_sizes, int n_in,
                              void* d_out, int out_size) {
    const float* x    = (const float*)d_in[0];
    const float* w_up = (const float*)d_in[1];
    const float* w_dn = (const float*)d_in[2];
    float* out = (float*)d_out;

    cudaFuncSetAttribute(k_gemm1, cudaFuncAttributeMaxDynamicSharedMemorySize, SMEM_BYTES);
    cudaFuncSetAttribute(k_gemm2, cudaFuncAttributeMaxDynamicSharedMemorySize, SMEM_BYTES);

    k_abs_both<<<dim3(256, 2), 256>>>(w_up, w_dn);                    // 0
    k_finalize<<<1, 256>>>();                                         // 1
    k_wquant_both<<<dim3(WELEMS / 4 / 256, 2), 256>>>(w_up, w_dn);    // 2
    k_xquant<<<TOKENS, 128>>>(x);                                     // 3
    k_gemm1<<<dim3(DFF / 128, 256), 256, SMEM_BYTES>>>(0);            // 4  <- ncu
    k_gemm1<<<dim3(DFF / 128, 256), 256, SMEM_BYTES>>>(256);          // 5  <- ncu
    k_hrequant<<<(TOKENS * DFF / 16) / 256, 256>>>();                 // 6
    k_gemm2<<<dim3(DMODEL / 128, TOKENS / 128), 256, SMEM_BYTES>>>(out); // 7
}

// round 6
// speedup vs baseline: 1.0677x; 1.0677x over previous
#include <cuda_runtime.h>
#include <cstdint>

// ============================================================================
// Problem: x[8,8192,512] f32, w_up[2048,512] f32, w_down[512,2048] f32
// BitNet b1.58 FFN. All math after quantization is exact in int8 x int8 -> s32.
// ============================================================================
#define TOKENS 65536
#define DMODEL 512
#define DFF    2048
#define WELEMS (DFF * DMODEL)

// GEMM tiling
#define NSTAGE 3
#define CH     64            // K bytes per chunk (int8)
#define PITCH  80            // smem row pitch: 5*16 -> conflict-free ldmatrix
#define TILEB  (128 * PITCH) // 10240 per operand tile
#define STAGEB (2 * TILEB)   // 20480
#define SMEM_BYTES (NSTAGE * STAGEB)  // 61440 -> 2 CTAs/SM

// ============================================================================
// Device scratch (allocation-free)
// ============================================================================
__device__ float       g_part[2][256];
__device__ float       g_wscale[2];
__device__ int8_t      g_wup_q[WELEMS];          // ternary {-1,0,1}, [2048,512]
__device__ int8_t      g_wdn_q[WELEMS];          // ternary, [512,2048]
__device__ int8_t      g_xq[TOKENS * DMODEL];    // per-token int8 x
__device__ float       g_xinv[TOKENS];           // clip(max|x|,eps)/127
__device__ int         g_rowmax[TOKENS];         // max h int per token
__device__ int8_t      g_h[TOKENS * DFF];        // h ints [0,127]; then requantized

// ============================================================================
// Small helpers
// ============================================================================
__device__ __forceinline__ uint32_t smem_u32(const void* p) {
    uint32_t a;
    asm("{ .reg .u64 t; cvta.to.shared.u64 t, %1; cvt.u32.u64 %0, t; }" : "=r"(a) : "l"(p));
    return a;
}
__device__ __forceinline__ void cp16(uint32_t dst, const void* src) {
    asm volatile("cp.async.cg.shared.global [%0], [%1], 16;"
                 :: "r"(dst), "l"(__cvta_generic_to_global(src)));
}
#define CP_COMMIT() asm volatile("cp.async.commit_group;")
#define CP_WAIT1()  asm volatile("cp.async.wait_group 1;")

__device__ __forceinline__ void ldsm4(uint32_t& r0, uint32_t& r1, uint32_t& r2, uint32_t& r3,
                                      uint32_t addr) {
    asm volatile("ldmatrix.sync.aligned.m8n8.x4.shared.b16 {%0,%1,%2,%3}, [%4];"
                 : "=r"(r0), "=r"(r1), "=r"(r2), "=r"(r3) : "r"(addr));
}
__device__ __forceinline__ void mma_s8(int* c, const uint32_t* a, uint32_t b0, uint32_t b1) {
    asm volatile("mma.sync.aligned.m16n8k32.row.col.s32.s8.s8.s32 "
                 "{%0,%1,%2,%3},{%4,%5,%6,%7},{%8,%9},{%0,%1,%2,%3};"
                 : "+r"(c[0]), "+r"(c[1]), "+r"(c[2]), "+r"(c[3])
                 : "r"(a[0]), "r"(a[1]), "r"(a[2]), "r"(a[3]), "r"(b0), "r"(b1));
}

// ============================================================================
// Prep kernels
// ============================================================================
__global__ void k_abs_both(const float* __restrict__ w0, const float* __restrict__ w1) {
    __shared__ float red[256];
    int which = blockIdx.y;
    const float* w = which ? w1 : w0;
    int tid = threadIdx.x;
    float s = 0.0f;
    for (int i = blockIdx.x * 256 + tid; i < WELEMS; i += 256 * 256)
        s += fabsf(w[i]);
    red[tid] = s;
    __syncthreads();
    for (int o = 128; o > 0; o >>= 1) {
        if (tid < o) red[tid] += red[tid + o];
        __syncthreads();
    }
    if (tid == 0) g_part[which][blockIdx.x] = red[0];
}

__global__ void k_finalize() {
    __shared__ float s0[256], s1[256];
    int t = threadIdx.x;
    s0[t] = g_part[0][t];
    s1[t] = g_part[1][t];
    __syncthreads();
    for (int o = 128; o > 0; o >>= 1) {
        if (t < o) { s0[t] += s0[t + o]; s1[t] += s1[t + o]; }
        __syncthreads();
    }
    if (t == 0) {
        g_wscale[0] = fmaxf(s0[0] / (float)WELEMS, 1e-5f);
        g_wscale[1] = fmaxf(s1[0] / (float)WELEMS, 1e-5f);
    }
}

// Fused: blocks [0,32768) do x-quant (2 tokens/block); [32768,34816) do w-quant.
#define XQ_BLOCKS (TOKENS / 2)                 // 32768
#define WQ_BLOCKS (2 * (WELEMS / 4 / 256))     // 2048
__global__ void __launch_bounds__(256) k_quant_fused(const float* __restrict__ x,
                                                     const float* __restrict__ w0,
                                                     const float* __restrict__ w1) {
    if (blockIdx.x < XQ_BLOCKS) {
        __shared__ float wmax[8];
        int tid = threadIdx.x;
        int half = tid >> 7, htid = tid & 127;
        int wid = tid >> 5, lid = tid & 31;
        int token = blockIdx.x * 2 + half;
        float4 v = ((const float4*)(x + (size_t)token * DMODEL))[htid];
        float a = fmaxf(fmaxf(fabsf(v.x), fabsf(v.y)), fmaxf(fabsf(v.z), fabsf(v.w)));
        #pragma unroll
        for (int o = 16; o > 0; o >>= 1) a = fmaxf(a, __shfl_xor_sync(0xffffffffu, a, o));
        if (lid == 0) wmax[wid] = a;
        __syncthreads();
        int wb = half * 4;
        a = fmaxf(fmaxf(wmax[wb], wmax[wb + 1]), fmaxf(wmax[wb + 2], wmax[wb + 3]));
        float amaxc = fmaxf(a, 1e-5f);
        float s = 127.0f / amaxc;
        int q0 = (int)fminf(fmaxf(rintf(v.x * s), -128.f), 127.f);
        int q1 = (int)fminf(fmaxf(rintf(v.y * s), -128.f), 127.f);
        int q2 = (int)fminf(fmaxf(rintf(v.z * s), -128.f), 127.f);
        int q3 = (int)fminf(fmaxf(rintf(v.w * s), -128.f), 127.f);
        *(char4*)(g_xq + (size_t)token * DMODEL + htid * 4) =
            make_char4((char)q0, (char)q1, (char)q2, (char)q3);
        if (htid == 0) {
            g_xinv[token] = amaxc / 127.0f;
            g_rowmax[token] = 0;
        }
    } else {
        int idx = blockIdx.x - XQ_BLOCKS;
        int which = idx >> 10;                       // 1024 blocks each weight
        const float* w = which ? w1 : w0;
        int i = (idx & 1023) * 256 + threadIdx.x;
        float inv = 1.0f / g_wscale[which];
        float4 v = ((const float4*)w)[i];
        int t0 = (int)fminf(fmaxf(rintf(v.x * inv), -1.f), 1.f);
        int t1 = (int)fminf(fmaxf(rintf(v.y * inv), -1.f), 1.f);
        int t2 = (int)fminf(fmaxf(rintf(v.z * inv), -1.f), 1.f);
        int t3 = (int)fminf(fmaxf(rintf(v.w * inv), -1.f), 1.f);
        int8_t* dst = which ? g_wdn_q : g_wup_q;
        *(char4*)(dst + i * 4) = make_char4((char)t0, (char)t1, (char)t2, (char)t3);
    }
}

// Requantize h in place: h' = rint(h * 127/clip(rowmax,eps))
__global__ void k_hrequant() {
    int idx = blockIdx.x * 256 + threadIdx.x;     // one 16B chunk
    int token = (idx * 16) >> 11;                 // 2048 per token
    float f = 127.0f / fmaxf((float)g_rowmax[token], 1e-5f);
    uint4 raw = *(const uint4*)(g_h + (size_t)idx * 16);
    uint32_t rw[4] = {raw.x, raw.y, raw.z, raw.w};
    uint32_t out[4];
    #pragma unroll
    for (int u = 0; u < 4; ++u) {
        uint32_t b = rw[u], o = 0;
        #pragma unroll
        for (int j = 0; j < 4; ++j) {
            int q = (int)fminf(rintf((float)((b >> (8 * j)) & 0xff) * f), 127.0f);
            o |= ((uint32_t)q & 0xff) << (8 * j);
        }
        out[u] = o;
    }
    *(uint4*)(g_h + (size_t)idx * 16) = make_uint4(out[0], out[1], out[2], out[3]);
}

// ============================================================================
// int8 GEMM core: C[128,128] += A[128,K] * B[128,K]^T  (both row-major K-last)
// 256 threads, 8 warps in 4(m) x 2(n); warp tile 32x64; mma m16n8k32.
// 3-stage cp.async pipeline; 2 CTAs/SM for latency hiding.
// ============================================================================
template<int NK, int K>
__device__ __forceinline__ void gemm_s8_core(const int8_t* __restrict__ Ag,
                                             const int8_t* __restrict__ Bg,
                                             int m0, int n0, char* smem,
                                             int (&acc)[2][8][4]) {
    const int tid = threadIdx.x, lane = tid & 31, wid = tid >> 5;
    const int wm = wid & 3, wn = wid >> 2;

    // ---- stage loader: 1024 x 16B cp.async (A 512, B 512) ----
    auto load_chunk = [&](int kc, int buf) {
        char* st = smem + buf * STAGEB;
        #pragma unroll
        for (int t = 0; t < 4; ++t) {
            int i = tid + t * 256;
            int isB = i >> 9, idx = i & 511;
            int row = idx >> 2, c = idx & 3;
            const int8_t* src = (isB ? Bg + (size_t)(n0 + row) * K
                                     : Ag + (size_t)(m0 + row) * K) + kc * CH + c * 16;
            cp16(smem_u32(st + isB * TILEB + row * PITCH + c * 16), src);
        }
    };

    // fragment base addresses (per-lane)
    const uint32_t a_addr0 = smem_u32(smem + (wm * 32 + (lane & 15)) * PITCH + (lane >> 4) * 16);
    const uint32_t b_addr0 = smem_u32(smem + TILEB +
                                      (wn * 64 + ((lane >> 4) * 8) + (lane & 7)) * PITCH +
                                      ((lane >> 3) & 1) * 16);

    auto compute_chunk = [&](int buf) {
        uint32_t abase = a_addr0 + buf * STAGEB;
        uint32_t bbase = b_addr0 + buf * STAGEB;
        #pragma unroll
        for (int s = 0; s < 2; ++s) {                    // two k32 steps per 64B chunk
            uint32_t a[2][4];
            #pragma unroll
            for (int im = 0; im < 2; ++im)
                ldsm4(a[im][0], a[im][1], a[im][2], a[im][3],
                      abase + im * 16 * PITCH + s * 32);
            uint32_t b[4][4];
            #pragma unroll
            for (int jn = 0; jn < 4; ++jn)
                ldsm4(b[jn][0], b[jn][1], b[jn][2], b[jn][3],
                      bbase + jn * 16 * PITCH + s * 32);
            #pragma unroll
            for (int im = 0; im < 2; ++im)
                #pragma unroll
                for (int j = 0; j < 8; ++j)
                    mma_s8(acc[im][j], a[im], b[j >> 1][(j & 1) * 2], b[j >> 1][(j & 1) * 2 + 1]);
        }
    };

    // ---- 3-stage pipeline ----
    load_chunk(0, 0); CP_COMMIT();
    load_chunk(1, 1); CP_COMMIT();

    int cb = 0, lb = 2;
    #pragma unroll 1
    for (int kc = 0; kc < NK; ++kc) {
        CP_WAIT1();
        __syncthreads();
        if (kc + 2 < NK) load_chunk(kc + 2, lb);
        CP_COMMIT();
        compute_chunk(cb);
        cb = (cb == 2) ? 0 : cb + 1;
        lb = (lb == 2) ? 0 : lb + 1;
    }
}

// ---- GEMM1: h = clamp(rint(relu(Xq @ WupT)) * scales) -> int8 + rowmax ----
__global__ void __launch_bounds__(256, 2) k_gemm1() {
    extern __shared__ char smem[];
    const int tid = threadIdx.x, lane = tid & 31, wid = tid >> 5;
    const int wm = wid & 3, wn = wid >> 2;
    const int m0 = blockIdx.y * 128, n0 = blockIdx.x * 128;

    int acc[2][8][4];
    #pragma unroll
    for (int im = 0; im < 2; ++im)
        #pragma unroll
        for (int j = 0; j < 8; ++j)
            #pragma unroll
            for (int q = 0; q < 4; ++q) acc[im][j][q] = 0;

    gemm_s8_core<DMODEL / CH, DMODEL>(g_xq, g_wup_q, m0, n0, smem, acc);

    const float ws = g_wscale[0];
    const int rbase = wm * 32 + (lane >> 2);
    float sA[2][2];
    int lmax[2][2];
    #pragma unroll
    for (int im = 0; im < 2; ++im)
        #pragma unroll
        for (int h = 0; h < 2; ++h) {
            sA[im][h] = ws * g_xinv[m0 + rbase + im * 16 + h * 8];
            lmax[im][h] = 0;
        }

    #pragma unroll
    for (int im = 0; im < 2; ++im)
        #pragma unroll
        for (int j = 0; j < 8; ++j) {
            int col = n0 + wn * 64 + j * 8 + 2 * (lane & 3);
            #pragma unroll
            for (int h = 0; h < 2; ++h) {
                int tok = m0 + rbase + im * 16 + h * 8;
                float v0 = fmaxf((float)acc[im][j][h * 2 + 0] * sA[im][h], 0.0f);
                float v1 = fmaxf((float)acc[im][j][h * 2 + 1] * sA[im][h], 0.0f);
                int q0 = min(__float2int_rn(v0), 127);
                int q1 = min(__float2int_rn(v1), 127);
                lmax[im][h] = max(lmax[im][h], max(q0, q1));
                *(char2*)(g_h + (size_t)tok * DFF + col) = make_char2((char)q0, (char)q1);
            }
        }

    // block-level rowmax reduce, then global atomicMax
    __syncthreads();
    int* smax = (int*)smem;
    if (tid < 128) smax[tid] = 0;
    __syncthreads();
    #pragma unroll
    for (int im = 0; im < 2; ++im)
        #pragma unroll
        for (int h = 0; h < 2; ++h)
            atomicMax(&smax[rbase + im * 16 + h * 8], lmax[im][h]);
    __syncthreads();
    if (tid < 128) atomicMax(&g_rowmax[m0 + tid], smax[tid]);
}

// ---- GEMM2: out = (Hq @ WdnT) * (wscale_dn * rowmax/127) -------------------
__global__ void __launch_bounds__(256, 2) k_gemm2(float* __restrict__ out) {
    extern __shared__ char smem[];
    const int tid = threadIdx.x, lane = tid & 31, wid = tid >> 5;
    const int wm = wid & 3, wn = wid >> 2;
    const int m0 = blockIdx.y * 128, n0 = blockIdx.x * 128;

    int acc[2][8][4];
    #pragma unroll
    for (int im = 0; im < 2; ++im)
        #pragma unroll
        for (int j = 0; j < 8; ++j)
            #pragma unroll
            for (int q = 0; q < 4; ++q) acc[im][j][q] = 0;

    gemm_s8_core<DFF / CH, DFF>(g_h, g_wdn_q, m0, n0, smem, acc);

    const float ws = g_wscale[1];
    const int rbase = wm * 32 + (lane >> 2);
    float ofac[2][2];
    #pragma unroll
    for (int im = 0; im < 2; ++im)
        #pragma unroll
        for (int h = 0; h < 2; ++h) {
            int tok = m0 + rbase + im * 16 + h * 8;
            ofac[im][h] = ws * fmaxf((float)g_rowmax[tok], 1e-5f) * (1.0f / 127.0f);
        }

    #pragma unroll
    for (int im = 0; im < 2; ++im)
        #pragma unroll
        for (int j = 0; j < 8; ++j) {
            int col = n0 + wn * 64 + j * 8 + 2 * (lane & 3);
            #pragma unroll
            for (int h = 0; h < 2; ++h) {
                int tok = m0 + rbase + im * 16 + h * 8;
                float2 o = make_float2((float)acc[im][j][h * 2 + 0] * ofac[im][h],
                                       (float)acc[im][j][h * 2 + 1] * ofac[im][h]);
                *(float2*)(out + (size_t)tok * DMODEL + col) = o;
            }
        }
}

// ============================================================================
// Launch — the harness's ncu capture lands on launch index 3, which below is
// k_gemm1 (the dominant kernel).
// ============================================================================
extern "C" void kernel_launch(void* const* d_in, const int* in_sizes, int n_in,
                              void* d_out, int out_size) {
    const float* x    = (const float*)d_in[0];
    const float* w_up = (const float*)d_in[1];
    const float* w_dn = (const float*)d_in[2];
    float* out = (float*)d_out;

    cudaFuncSetAttribute(k_gemm1, cudaFuncAttributeMaxDynamicSharedMemorySize, SMEM_BYTES);
    cudaFuncSetAttribute(k_gemm2, cudaFuncAttributeMaxDynamicSharedMemorySize, SMEM_BYTES);

    k_abs_both<<<dim3(256, 2), 256>>>(w_up, w_dn);                        // 0
    k_finalize<<<1, 256>>>();                                             // 1
    k_quant_fused<<<XQ_BLOCKS + WQ_BLOCKS, 256>>>(x, w_up, w_dn);         // 2
    k_gemm1<<<dim3(DFF / 128, TOKENS / 128), 256, SMEM_BYTES>>>();        // 3  <- ncu
    k_hrequant<<<(TOKENS * DFF / 16) / 256, 256>>>();                     // 4
    k_gemm2<<<dim3(DMODEL / 128, TOKENS / 128), 256, SMEM_BYTES>>>(out);  // 5
}

// round 8
// speedup vs baseline: 1.1199x; 1.0489x over previous
#include <cuda_runtime.h>
#include <cstdint>

// ============================================================================
// Problem: x[8,8192,512] f32, w_up[2048,512] f32, w_down[512,2048] f32
// BitNet b1.58 FFN. All math after quantization is exact in int8 x int8 -> s32.
// ============================================================================
#define TOKENS 65536
#define DMODEL 512
#define DFF    2048
#define WELEMS (DFF * DMODEL)

// GEMM tiling
#define NSTAGE 3
#define CH     128           // K bytes per chunk (int8)
#define PITCH  144           // smem row pitch: 9*16 -> conflict-free ldmatrix (16r mod 128 distinct)
#define TILEB  (128 * PITCH) // 18432 per operand tile
#define STAGEB (2 * TILEB)   // 36864
#define SMEM_BYTES (NSTAGE * STAGEB)  // 110592 -> 2 CTAs/SM (221KB of 228KB)

// ============================================================================
// Device scratch (allocation-free)
// ============================================================================
__device__ float       g_part[2][256];
__device__ float       g_wscale[2];
__device__ int8_t      g_wup_q[WELEMS];          // ternary {-1,0,1}, [2048,512]
__device__ int8_t      g_wdn_q[WELEMS];          // ternary, [512,2048]
__device__ int8_t      g_xq[TOKENS * DMODEL];    // per-token int8 x
__device__ float       g_xinv[TOKENS];           // clip(max|x|,eps)/127
__device__ int         g_rowmax[TOKENS];         // max h int per token
__device__ int8_t      g_h[TOKENS * DFF];        // h ints [0,127]; then requantized

// ============================================================================
// Small helpers
// ============================================================================
__device__ __forceinline__ uint32_t smem_u32(const void* p) {
    uint32_t a;
    asm("{ .reg .u64 t; cvta.to.shared.u64 t, %1; cvt.u32.u64 %0, t; }" : "=r"(a) : "l"(p));
    return a;
}
__device__ __forceinline__ void cp16(uint32_t dst, const void* src) {
    asm volatile("cp.async.cg.shared.global [%0], [%1], 16;"
                 :: "r"(dst), "l"(__cvta_generic_to_global(src)));
}
#define CP_COMMIT() asm volatile("cp.async.commit_group;")
#define CP_WAIT1()  asm volatile("cp.async.wait_group 1;")

__device__ __forceinline__ void ldsm4(uint32_t& r0, uint32_t& r1, uint32_t& r2, uint32_t& r3,
                                      uint32_t addr) {
    asm volatile("ldmatrix.sync.aligned.m8n8.x4.shared.b16 {%0,%1,%2,%3}, [%4];"
                 : "=r"(r0), "=r"(r1), "=r"(r2), "=r"(r3) : "r"(addr));
}
__device__ __forceinline__ void mma_s8(int* c, const uint32_t* a, uint32_t b0, uint32_t b1) {
    asm volatile("mma.sync.aligned.m16n8k32.row.col.s32.s8.s8.s32 "
                 "{%0,%1,%2,%3},{%4,%5,%6,%7},{%8,%9},{%0,%1,%2,%3};"
                 : "+r"(c[0]), "+r"(c[1]), "+r"(c[2]), "+r"(c[3])
                 : "r"(a[0]), "r"(a[1]), "r"(a[2]), "r"(a[3]), "r"(b0), "r"(b1));
}

// ============================================================================
// Prep kernels
// ============================================================================
__global__ void k_abs_both(const float* __restrict__ w0, const float* __restrict__ w1) {
    __shared__ float red[256];
    int which = blockIdx.y;
    const float* w = which ? w1 : w0;
    int tid = threadIdx.x;
    float s = 0.0f;
    for (int i = blockIdx.x * 256 + tid; i < WELEMS; i += 256 * 256)
        s += fabsf(w[i]);
    red[tid] = s;
    __syncthreads();
    for (int o = 128; o > 0; o >>= 1) {
        if (tid < o) red[tid] += red[tid + o];
        __syncthreads();
    }
    if (tid == 0) g_part[which][blockIdx.x] = red[0];
}

__global__ void k_finalize() {
    __shared__ float s0[256], s1[256];
    int t = threadIdx.x;
    s0[t] = g_part[0][t];
    s1[t] = g_part[1][t];
    __syncthreads();
    for (int o = 128; o > 0; o >>= 1) {
        if (t < o) { s0[t] += s0[t + o]; s1[t] += s1[t + o]; }
        __syncthreads();
    }
    if (t == 0) {
        g_wscale[0] = fmaxf(s0[0] / (float)WELEMS, 1e-5f);
        g_wscale[1] = fmaxf(s1[0] / (float)WELEMS, 1e-5f);
    }
}

// Fused: blocks [0,32768) do x-quant (2 tokens/block); [32768,34816) do w-quant.
#define XQ_BLOCKS (TOKENS / 2)                 // 32768
#define WQ_BLOCKS (2 * (WELEMS / 4 / 256))     // 2048
__global__ void __launch_bounds__(256) k_quant_fused(const float* __restrict__ x,
                                                     const float* __restrict__ w0,
                                                     const float* __restrict__ w1) {
    if (blockIdx.x < XQ_BLOCKS) {
        __shared__ float wmax[8];
        int tid = threadIdx.x;
        int half = tid >> 7, htid = tid & 127;
        int wid = tid >> 5, lid = tid & 31;
        int token = blockIdx.x * 2 + half;
        float4 v = ((const float4*)(x + (size_t)token * DMODEL))[htid];
        float a = fmaxf(fmaxf(fabsf(v.x), fabsf(v.y)), fmaxf(fabsf(v.z), fabsf(v.w)));
        #pragma unroll
        for (int o = 16; o > 0; o >>= 1) a = fmaxf(a, __shfl_xor_sync(0xffffffffu, a, o));
        if (lid == 0) wmax[wid] = a;
        __syncthreads();
        int wb = half * 4;
        a = fmaxf(fmaxf(wmax[wb], wmax[wb + 1]), fmaxf(wmax[wb + 2], wmax[wb + 3]));
        float amaxc = fmaxf(a, 1e-5f);
        float s = 127.0f / amaxc;
        int q0 = (int)fminf(fmaxf(rintf(v.x * s), -128.f), 127.f);
        int q1 = (int)fminf(fmaxf(rintf(v.y * s), -128.f), 127.f);
        int q2 = (int)fminf(fmaxf(rintf(v.z * s), -128.f), 127.f);
        int q3 = (int)fminf(fmaxf(rintf(v.w * s), -128.f), 127.f);
        *(char4*)(g_xq + (size_t)token * DMODEL + htid * 4) =
            make_char4((char)q0, (char)q1, (char)q2, (char)q3);
        if (htid == 0) {
            g_xinv[token] = amaxc / 127.0f;
            g_rowmax[token] = 0;
        }
    } else {
        int idx = blockIdx.x - XQ_BLOCKS;
        int which = idx >> 10;                       // 1024 blocks each weight
        const float* w = which ? w1 : w0;
        int i = (idx & 1023) * 256 + threadIdx.x;
        float inv = 1.0f / g_wscale[which];
        float4 v = ((const float4*)w)[i];
        int t0 = (int)fminf(fmaxf(rintf(v.x * inv), -1.f), 1.f);
        int t1 = (int)fminf(fmaxf(rintf(v.y * inv), -1.f), 1.f);
        int t2 = (int)fminf(fmaxf(rintf(v.z * inv), -1.f), 1.f);
        int t3 = (int)fminf(fmaxf(rintf(v.w * inv), -1.f), 1.f);
        int8_t* dst = which ? g_wdn_q : g_wup_q;
        *(char4*)(dst + i * 4) = make_char4((char)t0, (char)t1, (char)t2, (char)t3);
    }
}

// Requantize h in place: h' = rint(h * 127/clip(rowmax,eps))
__global__ void k_hrequant() {
    int idx = blockIdx.x * 256 + threadIdx.x;     // one 16B chunk
    int token = (idx * 16) >> 11;                 // 2048 per token
    float f = 127.0f / fmaxf((float)g_rowmax[token], 1e-5f);
    uint4 raw = *(const uint4*)(g_h + (size_t)idx * 16);
    uint32_t rw[4] = {raw.x, raw.y, raw.z, raw.w};
    uint32_t out[4];
    #pragma unroll
    for (int u = 0; u < 4; ++u) {
        uint32_t b = rw[u], o = 0;
        #pragma unroll
        for (int j = 0; j < 4; ++j) {
            int q = (int)fminf(rintf((float)((b >> (8 * j)) & 0xff) * f), 127.0f);
            o |= ((uint32_t)q & 0xff) << (8 * j);
        }
        out[u] = o;
    }
    *(uint4*)(g_h + (size_t)idx * 16) = make_uint4(out[0], out[1], out[2], out[3]);
}

// ============================================================================
// int8 GEMM core: C[128,128] += A[128,K] * B[128,K]^T  (both row-major K-last)
// 256 threads, 8 warps in 4(m) x 2(n); warp tile 32x64; mma m16n8k32.
// 128B K-chunks (4 k32-steps per barrier), 3-stage cp.async, 2 CTAs/SM.
// ============================================================================
template<int NK, int K>
__device__ __forceinline__ void gemm_s8_core(const int8_t* __restrict__ Ag,
                                             const int8_t* __restrict__ Bg,
                                             int m0, int n0, char* smem,
                                             int (&acc)[2][8][4]) {
    const int tid = threadIdx.x, lane = tid & 31, wid = tid >> 5;
    const int wm = wid & 3, wn = wid >> 2;

    // ---- stage loader: 2048 x 16B cp.async (A 1024, B 1024); 8 per thread ----
    // Consecutive 8 threads fill one 128B row segment -> fully coalesced STS.
    auto load_chunk = [&](int kc, int buf) {
        char* st = smem + buf * STAGEB;
        #pragma unroll
        for (int t = 0; t < 8; ++t) {
            int i = tid + t * 256;
            int isB = i >> 10, idx = i & 1023;
            int row = idx >> 3, c = idx & 7;
            const int8_t* src = (isB ? Bg + (size_t)(n0 + row) * K
                                     : Ag + (size_t)(m0 + row) * K) + kc * CH + c * 16;
            cp16(smem_u32(st + isB * TILEB + row * PITCH + c * 16), src);
        }
    };

    // fragment base addresses (per-lane)
    const uint32_t a_addr0 = smem_u32(smem + (wm * 32 + (lane & 15)) * PITCH + (lane >> 4) * 16);
    const uint32_t b_addr0 = smem_u32(smem + TILEB +
                                      (wn * 64 + ((lane >> 4) * 8) + (lane & 7)) * PITCH +
                                      ((lane >> 3) & 1) * 16);

    auto compute_chunk = [&](int buf) {
        uint32_t abase = a_addr0 + buf * STAGEB;
        uint32_t bbase = b_addr0 + buf * STAGEB;
        #pragma unroll
        for (int s = 0; s < 4; ++s) {                    // four k32 steps per 128B chunk
            uint32_t a[2][4];
            #pragma unroll
            for (int im = 0; im < 2; ++im)
                ldsm4(a[im][0], a[im][1], a[im][2], a[im][3],
                      abase + im * 16 * PITCH + s * 32);
            uint32_t b[4][4];
            #pragma unroll
            for (int jn = 0; jn < 4; ++jn)
                ldsm4(b[jn][0], b[jn][1], b[jn][2], b[jn][3],
                      bbase + jn * 16 * PITCH + s * 32);
            #pragma unroll
            for (int im = 0; im < 2; ++im)
                #pragma unroll
                for (int j = 0; j < 8; ++j)
                    mma_s8(acc[im][j], a[im], b[j >> 1][(j & 1) * 2], b[j >> 1][(j & 1) * 2 + 1]);
        }
    };

    // ---- 3-stage pipeline ----
    load_chunk(0, 0); CP_COMMIT();
    load_chunk(1, 1); CP_COMMIT();

    int cb = 0, lb = 2;
    #pragma unroll 1
    for (int kc = 0; kc < NK; ++kc) {
        CP_WAIT1();
        __syncthreads();
        if (kc + 2 < NK) load_chunk(kc + 2, lb);
        CP_COMMIT();
        compute_chunk(cb);
        cb = (cb == 2) ? 0 : cb + 1;
        lb = (lb == 2) ? 0 : lb + 1;
    }
}

// ---- GEMM1: h = clamp(rint(relu(Xq @ WupT)) * scales) -> int8 + rowmax ----
__global__ void __launch_bounds__(256, 2) k_gemm1() {
    extern __shared__ char smem[];
    const int tid = threadIdx.x, lane = tid & 31, wid = tid >> 5;
    const int wm = wid & 3, wn = wid >> 2;
    const int m0 = blockIdx.y * 128, n0 = blockIdx.x * 128;

    int acc[2][8][4];
    #pragma unroll
    for (int im = 0; im < 2; ++im)
        #pragma unroll
        for (int j = 0; j < 8; ++j)
            #pragma unroll
            for (int q = 0; q < 4; ++q) acc[im][j][q] = 0;

    gemm_s8_core<DMODEL / CH, DMODEL>(g_xq, g_wup_q, m0, n0, smem, acc);

    const float ws = g_wscale[0];
    const int rbase = wm * 32 + (lane >> 2);
    float sA[2][2];
    int lmax[2][2];
    #pragma unroll
    for (int im = 0; im < 2; ++im)
        #pragma unroll
        for (int h = 0; h < 2; ++h) {
            sA[im][h] = ws * g_xinv[m0 + rbase + im * 16 + h * 8];
            lmax[im][h] = 0;
        }

    #pragma unroll
    for (int im = 0; im < 2; ++im)
        #pragma unroll
        for (int j = 0; j < 8; ++j) {
            int col = n0 + wn * 64 + j * 8 + 2 * (lane & 3);
            #pragma unroll
            for (int h = 0; h < 2; ++h) {
                int tok = m0 + rbase + im * 16 + h * 8;
                float v0 = fmaxf((float)acc[im][j][h * 2 + 0] * sA[im][h], 0.0f);
                float v1 = fmaxf((float)acc[im][j][h * 2 + 1] * sA[im][h], 0.0f);
                int q0 = min(__float2int_rn(v0), 127);
                int q1 = min(__float2int_rn(v1), 127);
                lmax[im][h] = max(lmax[im][h], max(q0, q1));
                *(char2*)(g_h + (size_t)tok * DFF + col) = make_char2((char)q0, (char)q1);
            }
        }

    // block-level rowmax reduce, then global atomicMax
    __syncthreads();
    int* smax = (int*)smem;
    if (tid < 128) smax[tid] = 0;
    __syncthreads();
    #pragma unroll
    for (int im = 0; im < 2; ++im)
        #pragma unroll
        for (int h = 0; h < 2; ++h)
            atomicMax(&smax[rbase + im * 16 + h * 8], lmax[im][h]);
    __syncthreads();
    if (tid < 128) atomicMax(&g_rowmax[m0 + tid], smax[tid]);
}

// ---- GEMM2: out = (Hq @ WdnT) * (wscale_dn * rowmax/127) -------------------
__global__ void __launch_bounds__(256, 2) k_gemm2(float* __restrict__ out) {
    extern __shared__ char smem[];
    const int tid = threadIdx.x, lane = tid & 31, wid = tid >> 5;
    const int wm = wid & 3, wn = wid >> 2;
    const int m0 = blockIdx.y * 128, n0 = blockIdx.x * 128;

    int acc[2][8][4];
    #pragma unroll
    for (int im = 0; im < 2; ++im)
        #pragma unroll
        for (int j = 0; j < 8; ++j)
            #pragma unroll
            for (int q = 0; q < 4; ++q) acc[im][j][q] = 0;

    gemm_s8_core<DFF / CH, DFF>(g_h, g_wdn_q, m0, n0, smem, acc);

    const float ws = g_wscale[1];
    const int rbase = wm * 32 + (lane >> 2);
    float ofac[2][2];
    #pragma unroll
    for (int im = 0; im < 2; ++im)
        #pragma unroll
        for (int h = 0; h < 2; ++h) {
            int tok = m0 + rbase + im * 16 + h * 8;
            ofac[im][h] = ws * fmaxf((float)g_rowmax[tok], 1e-5f) * (1.0f / 127.0f);
        }

    #pragma unroll
    for (int im = 0; im < 2; ++im)
        #pragma unroll
        for (int j = 0; j < 8; ++j) {
            int col = n0 + wn * 64 + j * 8 + 2 * (lane & 3);
            #pragma unroll
            for (int h = 0; h < 2; ++h) {
                int tok = m0 + rbase + im * 16 + h * 8;
                float2 o = make_float2((float)acc[im][j][h * 2 + 0] * ofac[im][h],
                                       (float)acc[im][j][h * 2 + 1] * ofac[im][h]);
                *(float2*)(out + (size_t)tok * DMODEL + col) = o;
            }
        }
}

// ============================================================================
// Launch — the harness's ncu capture lands on launch index 3 = k_gemm1.
// ============================================================================
extern "C" void kernel_launch(void* const* d_in, const int* in_sizes, int n_in,
                              void* d_out, int out_size) {
    const float* x    = (const float*)d_in[0];
    const float* w_up = (const float*)d_in[1];
    const float* w_dn = (const float*)d_in[2];
    float* out = (float*)d_out;

    cudaFuncSetAttribute(k_gemm1, cudaFuncAttributeMaxDynamicSharedMemorySize, SMEM_BYTES);
    cudaFuncSetAttribute(k_gemm2, cudaFuncAttributeMaxDynamicSharedMemorySize, SMEM_BYTES);

    k_abs_both<<<dim3(256, 2), 256>>>(w_up, w_dn);                        // 0
    k_finalize<<<1, 256>>>();                                             // 1
    k_quant_fused<<<XQ_BLOCKS + WQ_BLOCKS, 256>>>(x, w_up, w_dn);         // 2
    k_gemm1<<<dim3(DFF / 128, TOKENS / 128), 256, SMEM_BYTES>>>();        // 3  <- ncu
    k_hrequant<<<(TOKENS * DFF / 16) / 256, 256>>>();                     // 4
    k_gemm2<<<dim3(DMODEL / 128, TOKENS / 128), 256, SMEM_BYTES>>>(out);  // 5
}